// round 9
// baseline (speedup 1.0000x reference)
#include <cuda_runtime.h>
#include <cuda_bf16.h>
#include <math.h>
#include <stdint.h>

// Problem constants
#define R_NODES 10
#define HID 128
#define NE 36
#define BT 12800
#define NODE_F 1280
#define NTOT (BT * NODE_F)
#define LN_EPS 1e-5f
#define NI 3                            // instances per GAT CTA
#define VROWS 30
#define GRID_GAT ((BT + NI - 1) / NI)   // 4267

__device__ float g_nf0[NTOT];
__device__ float g_nf1[NTOT];
// W pre-arranged in mma.sync B-fragment layout:
// [layer][head]{ hi: [wslot(8)][kc(8)][lane(32)] 16B chunks = 32KB, lo: +32KB }
__device__ __align__(16) uint8_t g_Wt[3 * 4 * 65536];

__constant__ int c_start[R_NODES + 1] = {0, 5, 8, 12, 15, 17, 22, 27, 31, 33, 36};
__constant__ int c_src[NE] = {
    9, 5, 6, 1, 0,   0, 2, 1,   5, 1, 3, 2,   2, 4, 3,   3, 4,
    6, 2, 0, 7, 5,   5, 9, 0, 7, 6,   6, 5, 8, 7,   7, 8,   6, 0, 9
};

__device__ __forceinline__ float gelu_exact(float v) {
    return 0.5f * v * (1.0f + erff(v * 0.70710678118654752440f));
}
__device__ __forceinline__ uint32_t smem_u32(const void* p) {
    uint32_t a;
    asm("{ .reg .u64 t; cvta.to.shared.u64 t, %1; cvt.u32.u64 %0, t; }" : "=r"(a) : "l"(p));
    return a;
}
__device__ __forceinline__ void ldsm_x4(uint32_t* r, uint32_t addr) {
    asm volatile("ldmatrix.sync.aligned.m8n8.x4.shared.b16 {%0,%1,%2,%3}, [%4];"
                 : "=r"(r[0]), "=r"(r[1]), "=r"(r[2]), "=r"(r[3]) : "r"(addr));
}
__device__ __forceinline__ void mma_bf16(float* d, const uint32_t* a, uint32_t b0, uint32_t b1) {
    asm volatile("mma.sync.aligned.m16n8k16.row.col.f32.bf16.bf16.f32 "
                 "{%0,%1,%2,%3}, {%4,%5,%6,%7}, {%8,%9}, {%0,%1,%2,%3};"
                 : "+f"(d[0]), "+f"(d[1]), "+f"(d[2]), "+f"(d[3])
                 : "r"(a[0]), "r"(a[1]), "r"(a[2]), "r"(a[3]), "r"(b0), "r"(b1));
}
__device__ __forceinline__ void split_bf16x2(float v0, float v1, uint32_t& hi, uint32_t& lo) {
    __nv_bfloat16 h0 = __float2bfloat16(v0);
    __nv_bfloat16 h1 = __float2bfloat16(v1);
    __nv_bfloat16 l0 = __float2bfloat16(v0 - __bfloat162float(h0));
    __nv_bfloat16 l1 = __float2bfloat16(v1 - __bfloat162float(h1));
    hi = (uint32_t)__bfloat16_as_ushort(h0) | ((uint32_t)__bfloat16_as_ushort(h1) << 16);
    lo = (uint32_t)__bfloat16_as_ushort(l0) | ((uint32_t)__bfloat16_as_ushort(l1) << 16);
}

// ---------------------------------------------------------------------------
// W prep: per-(wslot,kc,lane) B fragments, bf16 hi/lo.
// ---------------------------------------------------------------------------
__global__ void wt_kernel(const float* __restrict__ Wg) {
    int l = blockIdx.x >> 2, h = blockIdx.x & 3;
    uint8_t* base = g_Wt + (size_t)(l * 4 + h) * 65536;
    const float* W = Wg + l * 65536 + h * 128;   // W[k*512 + n]
    for (int c = threadIdx.x; c < 2048; c += 256) {
        int ws = c >> 8, kc = (c >> 5) & 7, lane = c & 31;
        int n0 = ws * 16 + (lane >> 2);
        int k0 = kc * 16 + 2 * (lane & 3);
        uint32_t hi[4], lo[4];
#pragma unroll
        for (int j = 0; j < 4; ++j) {
            int n = n0 + (j >> 1) * 8;
            int k = k0 + (j & 1) * 8;
            float w0 = W[k * 512 + n];
            float w1 = W[(k + 1) * 512 + n];
            split_bf16x2(w0, w1, hi[j], lo[j]);
        }
        *(uint4*)(base + c * 16)         = make_uint4(hi[0], hi[1], hi[2], hi[3]);
        *(uint4*)(base + 32768 + c * 16) = make_uint4(lo[0], lo[1], lo[2], lo[3]);
    }
}

// ---------------------------------------------------------------------------
// Encoder (unchanged)
// ---------------------------------------------------------------------------
__global__ void __launch_bounds__(256) encoder_kernel(
    const float* __restrict__ x, const float* __restrict__ Wenc,
    const float* __restrict__ benc, const float* __restrict__ gamma,
    const float* __restrict__ beta, float* __restrict__ nf_out,
    float* __restrict__ region_out)
{
    const int tid = threadIdx.x;
    const int lane = tid & 31;
    const int w4 = (tid >> 5) & 3;
    const int inst = tid >> 7;
    const long bt = (long)blockIdx.x * 2 + inst;
    const float* xr = x + bt * (R_NODES * 6);
    float* outp = nf_out + bt * NODE_F;
    float* regp = region_out ? region_out + bt * NODE_F : nullptr;

    for (int r = w4; r < R_NODES; r += 4) {
        float xv[6];
#pragma unroll
        for (int c = 0; c < 6; ++c) xv[c] = xr[r * 6 + c];
        float h[4];
#pragma unroll
        for (int j = 0; j < 4; ++j) {
            int k = lane + 32 * j;
            float a = benc[r * HID + k];
#pragma unroll
            for (int c = 0; c < 6; ++c) a = fmaf(xv[c], Wenc[(r * 6 + c) * HID + k], a);
            h[j] = a;
        }
        float s = h[0] + h[1] + h[2] + h[3];
        float sq = h[0]*h[0] + h[1]*h[1] + h[2]*h[2] + h[3]*h[3];
#pragma unroll
        for (int o = 16; o > 0; o >>= 1) {
            s  += __shfl_xor_sync(0xffffffffu, s, o);
            sq += __shfl_xor_sync(0xffffffffu, sq, o);
        }
        float mean = s * (1.0f / 128.0f);
        float var = sq * (1.0f / 128.0f) - mean * mean;
        float rstd = rsqrtf(var + LN_EPS);
#pragma unroll
        for (int j = 0; j < 4; ++j) {
            int k = lane + 32 * j;
            float v = (h[j] - mean) * rstd * gamma[r * HID + k] + beta[r * HID + k];
            float g = gelu_exact(v);
            outp[r * HID + k] = g;
            if (regp) regp[r * HID + k] = g;
        }
    }
}

// ---------------------------------------------------------------------------
// GAT layer: bf16 split-3 mma.sync, 2 heads per GEMM pass (A reuse).
// CTA = 3 instances (30 valid rows, 32 padded = 2 m16-tiles), 256 threads,
// 3 CTAs/SM. 8 warps = 2 head-slots x 4 col-slices (32 cols/warp).
// Per pass (head pair): GEMM(+partials) -> sync -> softmax -> sync -> agg -> sync.
// smem byte map (72064):
//   0      A_hi (8192)        8192   A_lo (8192)
//   16384  xp   (32 x 260 floats = 33280)
//   49664  out  (30*128*4 = 15360)
//   65024  att  (4096)
//   69120  alsp (2hh*4cs*32 = 1024)   70144  aldp (1024)
//   71168  alpha (2*3*36*4 = 864)
// ---------------------------------------------------------------------------
#define A_LO_B   8192
#define XP_B     16384
#define XP_STRIDE 260
#define OUT_B    49664
#define ATT_B    65024
#define ALSP_B   69120
#define ALDP_B   70144
#define ALPHA_B  71168
#define SM_DYNBYTES 72064

__global__ void __launch_bounds__(256, 3) gat_mma_kernel(
    const float* __restrict__ nf_in, const uint8_t* __restrict__ Wt,
    const float* __restrict__ asrc, const float* __restrict__ adst,
    const float* __restrict__ bg, float* __restrict__ nf_out)
{
    extern __shared__ uint8_t smb[];
    const uint32_t sb = smem_u32(smb);
    float* s_xp    = (float*)(smb + XP_B);
    float* s_out   = (float*)(smb + OUT_B);
    float* s_att   = (float*)(smb + ATT_B);
    float* s_alsp  = (float*)(smb + ALSP_B);
    float* s_aldp  = (float*)(smb + ALDP_B);
    float* s_alpha = (float*)(smb + ALPHA_B);

    const int tid  = threadIdx.x;
    const int wid  = tid >> 5;
    const int lane = tid & 31;
    const int hh   = wid >> 2;          // head slot within pair (0/1)
    const int cs   = wid & 3;           // col slice: cols cs*32..+32 within head
    const long blk = blockIdx.x;

    for (int i = tid; i < 512; i += 256) {
        s_att[i]       = asrc[i];
        s_att[512 + i] = adst[i];
    }

    // A fill: 32 rows x 16 k-chunks = 512 tasks -> bf16 hi/lo swizzled
#pragma unroll
    for (int it = 0; it < 2; ++it) {
        int t = tid + 256 * it;
        int r = t >> 4, kb = t & 15;
        int il = r / 10, node = r - il * 10;
        long ig = blk * NI + il;
        uint32_t hi[4], lo[4];
        if (r < VROWS && ig < BT) {
            const float* src = nf_in + ig * NODE_F + node * HID + kb * 8;
            float4 a = *(const float4*)(src);
            float4 b = *(const float4*)(src + 4);
            split_bf16x2(a.x, a.y, hi[0], lo[0]);
            split_bf16x2(a.z, a.w, hi[1], lo[1]);
            split_bf16x2(b.x, b.y, hi[2], lo[2]);
            split_bf16x2(b.z, b.w, hi[3], lo[3]);
        } else {
#pragma unroll
            for (int j = 0; j < 4; ++j) { hi[j] = 0u; lo[j] = 0u; }
        }
        uint32_t off = (uint32_t)(r * 256 + ((kb ^ (r & 7)) * 16));
        *(uint4*)(smb + off)          = make_uint4(hi[0], hi[1], hi[2], hi[3]);
        *(uint4*)(smb + A_LO_B + off) = make_uint4(lo[0], lo[1], lo[2], lo[3]);
    }
    __syncthreads();

    const int q4 = lane >> 2;               // 0..7
    const int c2 = (lane & 3) * 2;

    // Hoisted A-fragment addressing
    const int m_  = lane >> 3, i2_ = lane & 7;
    const int kbh = m_ >> 1;                       // kb = kc*2 + kbh
    const int rbase = (m_ & 1) * 8 + i2_;
    uint32_t arow[2], rx7[2];
#pragma unroll
    for (int mt = 0; mt < 2; ++mt) {
        int r = mt * 16 + rbase;
        arow[mt] = sb + (uint32_t)(r * 256);
        rx7[mt]  = (uint32_t)(r & 7);
    }

    for (int hp = 0; hp < 2; ++hp) {
        const int h = hp * 2 + hh;              // actual head for this warp
        // B fragments: wslots 2cs, 2cs+1 of head h
        const uint4* B0 = (const uint4*)Wt + (h * 4096 + (2 * cs) * 256 + lane);
        const uint4* B1 = B0 + 256;

        // ---- GEMM: warp = rows 0..31 x cols [cs*32,+32) of head h ----
        float acc[2][4][4];
#pragma unroll
        for (int mt = 0; mt < 2; ++mt)
#pragma unroll
            for (int nt = 0; nt < 4; ++nt)
#pragma unroll
                for (int j = 0; j < 4; ++j) acc[mt][nt][j] = 0.f;

#pragma unroll
        for (int kc = 0; kc < 8; ++kc) {
            uint4 bh0 = B0[kc * 32];
            uint4 bh1 = B1[kc * 32];
            uint4 bl0 = B0[kc * 32 + 2048];
            uint4 bl1 = B1[kc * 32 + 2048];
            const uint32_t kb = (uint32_t)(kc * 2 + kbh);
#pragma unroll
            for (int mt = 0; mt < 2; ++mt) {
                uint32_t addr = arow[mt] + ((kb ^ rx7[mt]) << 4);
                uint32_t ahi[4], alo[4];
                ldsm_x4(ahi, addr);
                ldsm_x4(alo, addr + A_LO_B);
                mma_bf16(acc[mt][0], ahi, bh0.x, bh0.y);
                mma_bf16(acc[mt][1], ahi, bh0.z, bh0.w);
                mma_bf16(acc[mt][2], ahi, bh1.x, bh1.y);
                mma_bf16(acc[mt][3], ahi, bh1.z, bh1.w);
                mma_bf16(acc[mt][0], alo, bh0.x, bh0.y);
                mma_bf16(acc[mt][1], alo, bh0.z, bh0.w);
                mma_bf16(acc[mt][2], alo, bh1.x, bh1.y);
                mma_bf16(acc[mt][3], alo, bh1.z, bh1.w);
                mma_bf16(acc[mt][0], ahi, bl0.x, bl0.y);
                mma_bf16(acc[mt][1], ahi, bl0.z, bl0.w);
                mma_bf16(acc[mt][2], ahi, bl1.x, bl1.y);
                mma_bf16(acc[mt][3], ahi, bl1.z, bl1.w);
            }
        }

        // ---- xp store + logit partials from accumulators ----
        float pals[2][2], pald[2][2];
#pragma unroll
        for (int mt = 0; mt < 2; ++mt) { pals[mt][0]=pals[mt][1]=pald[mt][0]=pald[mt][1]=0.f; }
#pragma unroll
        for (int mt = 0; mt < 2; ++mt) {
            int r0 = mt * 16 + q4;
#pragma unroll
            for (int nt = 0; nt < 4; ++nt) {
                int ch = cs * 32 + nt * 8 + c2;          // col within head
                float a0 = s_att[h * 128 + ch],       a1 = s_att[h * 128 + ch + 1];
                float d0 = s_att[512 + h * 128 + ch], d1 = s_att[512 + h * 128 + ch + 1];
                pals[mt][0] = fmaf(acc[mt][nt][0], a0, fmaf(acc[mt][nt][1], a1, pals[mt][0]));
                pald[mt][0] = fmaf(acc[mt][nt][0], d0, fmaf(acc[mt][nt][1], d1, pald[mt][0]));
                pals[mt][1] = fmaf(acc[mt][nt][2], a0, fmaf(acc[mt][nt][3], a1, pals[mt][1]));
                pald[mt][1] = fmaf(acc[mt][nt][2], d0, fmaf(acc[mt][nt][3], d1, pald[mt][1]));
                int cf = hh * 128 + ch;                   // col within xp row
                *(float2*)(s_xp + r0 * XP_STRIDE + cf)       = make_float2(acc[mt][nt][0], acc[mt][nt][1]);
                *(float2*)(s_xp + (r0 + 8) * XP_STRIDE + cf) = make_float2(acc[mt][nt][2], acc[mt][nt][3]);
            }
        }
#pragma unroll
        for (int mt = 0; mt < 2; ++mt)
#pragma unroll
            for (int j = 0; j < 2; ++j) {
                pals[mt][j] += __shfl_xor_sync(0xffffffffu, pals[mt][j], 1);
                pals[mt][j] += __shfl_xor_sync(0xffffffffu, pals[mt][j], 2);
                pald[mt][j] += __shfl_xor_sync(0xffffffffu, pald[mt][j], 1);
                pald[mt][j] += __shfl_xor_sync(0xffffffffu, pald[mt][j], 2);
            }
        if ((lane & 3) == 0) {
#pragma unroll
            for (int mt = 0; mt < 2; ++mt) {
                int r0 = mt * 16 + q4;
                s_alsp[(hh * 4 + cs) * 32 + r0]     = pals[mt][0];
                s_alsp[(hh * 4 + cs) * 32 + r0 + 8] = pals[mt][1];
                s_aldp[(hh * 4 + cs) * 32 + r0]     = pald[mt][0];
                s_aldp[(hh * 4 + cs) * 32 + r0 + 8] = pald[mt][1];
            }
        }
        __syncthreads();

        // ---- segment softmax (60 workers: 2 heads x 3 inst x 10 dst) ----
        if (tid < 60) {
            int th = tid / 30, rem = tid - th * 30;
            int il = rem / 10, dst = rem - il * 10, rb = il * 10;
            const float* asl = s_alsp + th * 128;
            const float* adl = s_aldp + th * 128;
            int rd = rb + dst;
            float ald = adl[rd] + adl[32 + rd] + adl[64 + rd] + adl[96 + rd];
            int s0 = c_start[dst], s1 = c_start[dst + 1];
            float vb[5], m = -1e30f;
            for (int k = s0; k < s1; ++k) {
                int rs = rb + c_src[k];
                float als = asl[rs] + asl[32 + rs] + asl[64 + rs] + asl[96 + rs];
                float v = als + ald;
                v = v > 0.f ? v : 0.2f * v;
                vb[k - s0] = v;
                m = fmaxf(m, v);
            }
            float ssum = 0.f;
            for (int k = s0; k < s1; ++k) {
                float ex = __expf(vb[k - s0] - m);
                ssum += ex;
                s_alpha[(th * 3 + il) * NE + k] = ex;
            }
            float inv = 1.0f / ssum;
            for (int k = s0; k < s1; ++k) s_alpha[(th * 3 + il) * NE + k] *= inv;
        }
        __syncthreads();

        // ---- aggregation (both heads of pair; accumulate in s_out) ----
#pragma unroll
        for (int it = 0; it < 4; ++it) {
            int q = tid + 256 * it;                 // 960 float4 tasks
            if (q < 960) {
                int il = q / 320, rem = q - il * 320, dst = rem >> 5, f = (rem & 31) * 4;
                float4 a4;
                if (hp == 0) { a4.x = a4.y = a4.z = a4.w = 0.f; }
                else           a4 = ((float4*)s_out)[q];
                int s0 = c_start[dst], s1 = c_start[dst + 1];
                int rb = il * 10;
#pragma unroll
                for (int th = 0; th < 2; ++th) {
                    const float* al = s_alpha + (th * 3 + il) * NE;
                    const float* xb = s_xp + th * 128 + f;
                    for (int k = s0; k < s1; ++k) {
                        int row = rb + c_src[k];
                        float a = al[k];
                        float4 xv = *(const float4*)(xb + row * XP_STRIDE);
                        a4.x = fmaf(a, xv.x, a4.x);
                        a4.y = fmaf(a, xv.y, a4.y);
                        a4.z = fmaf(a, xv.z, a4.z);
                        a4.w = fmaf(a, xv.w, a4.w);
                    }
                }
                ((float4*)s_out)[q] = a4;
            }
        }
        __syncthreads();
    }

    // ---- epilogue: head mean + bias + GELU + residual ----
#pragma unroll
    for (int it = 0; it < 4; ++it) {
        int q = tid + 256 * it;
        if (q < 960) {
            int il = q / 320, rem = q - il * 320, dst = rem >> 5, f = (rem & 31) * 4;
            long ig = blk * NI + il;
            if (ig < BT) {
                float4 o = ((float4*)s_out)[q];
                float4 bgv = *(const float4*)(bg + f);
                float4 rs  = *(const float4*)(nf_in + ig * NODE_F + dst * HID + f);
                float4 w;
                w.x = gelu_exact(fmaf(0.25f, o.x, bgv.x)) + rs.x;
                w.y = gelu_exact(fmaf(0.25f, o.y, bgv.y)) + rs.y;
                w.z = gelu_exact(fmaf(0.25f, o.z, bgv.z)) + rs.z;
                w.w = gelu_exact(fmaf(0.25f, o.w, bgv.w)) + rs.w;
                *(float4*)(nf_out + ig * NODE_F + dst * HID + f) = w;
            }
        }
    }
}

// ---------------------------------------------------------------------------
extern "C" void kernel_launch(void* const* d_in, const int* in_sizes, int n_in,
                              void* d_out, int out_size)
{
    const float* x     = (const float*)d_in[0];
    const float* Wenc  = (const float*)d_in[1];
    const float* benc  = (const float*)d_in[2];
    const float* gamma = (const float*)d_in[3];
    const float* beta  = (const float*)d_in[4];
    const float* Wg    = (const float*)d_in[5];
    const float* asrc  = (const float*)d_in[6];
    const float* adst  = (const float*)d_in[7];
    const float* bg    = (const float*)d_in[8];

    float* out = (float*)d_out;
    float* region_out = (out_size >= 2 * NTOT) ? out + NTOT : nullptr;

    float* nf0;  cudaGetSymbolAddress((void**)&nf0, g_nf0);
    float* nf1;  cudaGetSymbolAddress((void**)&nf1, g_nf1);
    uint8_t* wt; cudaGetSymbolAddress((void**)&wt, g_Wt);

    cudaFuncSetAttribute(gat_mma_kernel, cudaFuncAttributeMaxDynamicSharedMemorySize, SM_DYNBYTES);

    wt_kernel<<<12, 256>>>(Wg);
    encoder_kernel<<<BT / 2, 256>>>(x, Wenc, benc, gamma, beta, nf0, region_out);

    gat_mma_kernel<<<GRID_GAT, 256, SM_DYNBYTES>>>(nf0, wt,               asrc,        adst,        bg,       nf1);
    gat_mma_kernel<<<GRID_GAT, 256, SM_DYNBYTES>>>(nf1, wt + 4 * 65536,   asrc + 512,  adst + 512,  bg + 128, nf0);
    gat_mma_kernel<<<GRID_GAT, 256, SM_DYNBYTES>>>(nf0, wt + 8 * 65536,   asrc + 1024, adst + 1024, bg + 256, out);
}

// round 10
// speedup vs baseline: 1.1313x; 1.1313x over previous
#include <cuda_runtime.h>
#include <cuda_bf16.h>
#include <math.h>
#include <stdint.h>

// Problem constants
#define R_NODES 10
#define HID 128
#define NE 36
#define BT 12800
#define NODE_F 1280
#define NTOT (BT * NODE_F)
#define LN_EPS 1e-5f
#define NI 3                            // instances per GAT CTA
#define VROWS 30
#define GRID_GAT ((BT + NI - 1) / NI)   // 4267

__device__ float g_nf0[NTOT];
__device__ float g_nf1[NTOT];
// W pre-arranged in mma.sync B-fragment layout:
// [layer][head]{ hi: [wslot(8)][kc(8)][lane(32)] 16B chunks = 32KB, lo: +32KB }
__device__ __align__(16) uint8_t g_Wt[3 * 4 * 65536];

__constant__ int c_start[R_NODES + 1] = {0, 5, 8, 12, 15, 17, 22, 27, 31, 33, 36};
__constant__ int c_src[NE] = {
    9, 5, 6, 1, 0,   0, 2, 1,   5, 1, 3, 2,   2, 4, 3,   3, 4,
    6, 2, 0, 7, 5,   5, 9, 0, 7, 6,   6, 5, 8, 7,   7, 8,   6, 0, 9
};

__device__ __forceinline__ float gelu_exact(float v) {
    return 0.5f * v * (1.0f + erff(v * 0.70710678118654752440f));
}
__device__ __forceinline__ uint32_t smem_u32(const void* p) {
    uint32_t a;
    asm("{ .reg .u64 t; cvta.to.shared.u64 t, %1; cvt.u32.u64 %0, t; }" : "=r"(a) : "l"(p));
    return a;
}
__device__ __forceinline__ void ldsm_x4(uint32_t* r, uint32_t addr) {
    asm volatile("ldmatrix.sync.aligned.m8n8.x4.shared.b16 {%0,%1,%2,%3}, [%4];"
                 : "=r"(r[0]), "=r"(r[1]), "=r"(r[2]), "=r"(r[3]) : "r"(addr));
}
__device__ __forceinline__ void mma_bf16(float* d, const uint32_t* a, uint32_t b0, uint32_t b1) {
    asm volatile("mma.sync.aligned.m16n8k16.row.col.f32.bf16.bf16.f32 "
                 "{%0,%1,%2,%3}, {%4,%5,%6,%7}, {%8,%9}, {%0,%1,%2,%3};"
                 : "+f"(d[0]), "+f"(d[1]), "+f"(d[2]), "+f"(d[3])
                 : "r"(a[0]), "r"(a[1]), "r"(a[2]), "r"(a[3]), "r"(b0), "r"(b1));
}
__device__ __forceinline__ void split_bf16x2(float v0, float v1, uint32_t& hi, uint32_t& lo) {
    __nv_bfloat16 h0 = __float2bfloat16(v0);
    __nv_bfloat16 h1 = __float2bfloat16(v1);
    __nv_bfloat16 l0 = __float2bfloat16(v0 - __bfloat162float(h0));
    __nv_bfloat16 l1 = __float2bfloat16(v1 - __bfloat162float(h1));
    hi = (uint32_t)__bfloat16_as_ushort(h0) | ((uint32_t)__bfloat16_as_ushort(h1) << 16);
    lo = (uint32_t)__bfloat16_as_ushort(l0) | ((uint32_t)__bfloat16_as_ushort(l1) << 16);
}

// ---------------------------------------------------------------------------
// W prep: per-(wslot,kc,lane) B fragments, bf16 hi/lo. (unchanged)
// ---------------------------------------------------------------------------
__global__ void wt_kernel(const float* __restrict__ Wg) {
    int l = blockIdx.x >> 2, h = blockIdx.x & 3;
    uint8_t* base = g_Wt + (size_t)(l * 4 + h) * 65536;
    const float* W = Wg + l * 65536 + h * 128;   // W[k*512 + n]
    for (int c = threadIdx.x; c < 2048; c += 256) {
        int ws = c >> 8, kc = (c >> 5) & 7, lane = c & 31;
        int n0 = ws * 16 + (lane >> 2);
        int k0 = kc * 16 + 2 * (lane & 3);
        uint32_t hi[4], lo[4];
#pragma unroll
        for (int j = 0; j < 4; ++j) {
            int n = n0 + (j >> 1) * 8;
            int k = k0 + (j & 1) * 8;
            float w0 = W[k * 512 + n];
            float w1 = W[(k + 1) * 512 + n];
            split_bf16x2(w0, w1, hi[j], lo[j]);
        }
        *(uint4*)(base + c * 16)         = make_uint4(hi[0], hi[1], hi[2], hi[3]);
        *(uint4*)(base + 32768 + c * 16) = make_uint4(lo[0], lo[1], lo[2], lo[3]);
    }
}

// ---------------------------------------------------------------------------
// Encoder (unchanged)
// ---------------------------------------------------------------------------
__global__ void __launch_bounds__(256) encoder_kernel(
    const float* __restrict__ x, const float* __restrict__ Wenc,
    const float* __restrict__ benc, const float* __restrict__ gamma,
    const float* __restrict__ beta, float* __restrict__ nf_out,
    float* __restrict__ region_out)
{
    const int tid = threadIdx.x;
    const int lane = tid & 31;
    const int w4 = (tid >> 5) & 3;
    const int inst = tid >> 7;
    const long bt = (long)blockIdx.x * 2 + inst;
    const float* xr = x + bt * (R_NODES * 6);
    float* outp = nf_out + bt * NODE_F;
    float* regp = region_out ? region_out + bt * NODE_F : nullptr;

    for (int r = w4; r < R_NODES; r += 4) {
        float xv[6];
#pragma unroll
        for (int c = 0; c < 6; ++c) xv[c] = xr[r * 6 + c];
        float h[4];
#pragma unroll
        for (int j = 0; j < 4; ++j) {
            int k = lane + 32 * j;
            float a = benc[r * HID + k];
#pragma unroll
            for (int c = 0; c < 6; ++c) a = fmaf(xv[c], Wenc[(r * 6 + c) * HID + k], a);
            h[j] = a;
        }
        float s = h[0] + h[1] + h[2] + h[3];
        float sq = h[0]*h[0] + h[1]*h[1] + h[2]*h[2] + h[3]*h[3];
#pragma unroll
        for (int o = 16; o > 0; o >>= 1) {
            s  += __shfl_xor_sync(0xffffffffu, s, o);
            sq += __shfl_xor_sync(0xffffffffu, sq, o);
        }
        float mean = s * (1.0f / 128.0f);
        float var = sq * (1.0f / 128.0f) - mean * mean;
        float rstd = rsqrtf(var + LN_EPS);
#pragma unroll
        for (int j = 0; j < 4; ++j) {
            int k = lane + 32 * j;
            float v = (h[j] - mean) * rstd * gamma[r * HID + k] + beta[r * HID + k];
            float g = gelu_exact(v);
            outp[r * HID + k] = g;
            if (regp) regp[r * HID + k] = g;
        }
    }
}

// ---------------------------------------------------------------------------
// GAT layer: SINGLE-PASS all-4-heads GEMM. CTA = 3 instances (32 padded rows,
// 2 m16-tiles). 8 warps = 4 heads x 2 col-halves (64 cols each). 2 CTAs/SM.
// Phases: A-fill -> sync -> GEMM(all heads)+xp(fp32 smem)+partials -> sync ->
//         softmax(120 thr) -> sync -> fused agg+mean+bias+GELU+residual -> gmem.
// smem byte map (91840):
//   0      A_hi (8192)      8192   A_lo (8192)
//   16384  xp   [4][32][132] fp32 = 67584
//   83968  att  (4096)
//   88064  alsp (8*32*4 = 1024)   89088  aldp (1024)
//   90112  alpha (4*3*36*4 = 1728)
// ---------------------------------------------------------------------------
#define A_LO_B   8192
#define XP_B     16384
#define XP_STRIDE 132
#define XP_HEAD  (32 * XP_STRIDE)
#define ATT_B    83968
#define ALSP_B   88064
#define ALDP_B   89088
#define ALPHA_B  90112
#define SM_DYNBYTES 91840

__global__ void __launch_bounds__(256, 2) gat_mma_kernel(
    const float* __restrict__ nf_in, const uint8_t* __restrict__ Wt,
    const float* __restrict__ asrc, const float* __restrict__ adst,
    const float* __restrict__ bg, float* __restrict__ nf_out)
{
    extern __shared__ uint8_t smb[];
    const uint32_t sb = smem_u32(smb);
    float* s_xp    = (float*)(smb + XP_B);
    float* s_att   = (float*)(smb + ATT_B);
    float* s_alsp  = (float*)(smb + ALSP_B);
    float* s_aldp  = (float*)(smb + ALDP_B);
    float* s_alpha = (float*)(smb + ALPHA_B);

    const int tid  = threadIdx.x;
    const int wid  = tid >> 5;
    const int lane = tid & 31;
    const int hh   = wid >> 1;          // head 0..3
    const int ch2  = wid & 1;           // col half: cols ch2*64..+64 within head
    const long blk = blockIdx.x;

    for (int i = tid; i < 512; i += 256) {
        s_att[i]       = asrc[i];
        s_att[512 + i] = adst[i];
    }

    // A fill: 32 rows x 16 k-chunks = 512 tasks -> bf16 hi/lo swizzled
#pragma unroll
    for (int it = 0; it < 2; ++it) {
        int t = tid + 256 * it;
        int r = t >> 4, kb = t & 15;
        int il = r / 10, node = r - il * 10;
        long ig = blk * NI + il;
        uint32_t hi[4], lo[4];
        if (r < VROWS && ig < BT) {
            const float* src = nf_in + ig * NODE_F + node * HID + kb * 8;
            float4 a = *(const float4*)(src);
            float4 b = *(const float4*)(src + 4);
            split_bf16x2(a.x, a.y, hi[0], lo[0]);
            split_bf16x2(a.z, a.w, hi[1], lo[1]);
            split_bf16x2(b.x, b.y, hi[2], lo[2]);
            split_bf16x2(b.z, b.w, hi[3], lo[3]);
        } else {
#pragma unroll
            for (int j = 0; j < 4; ++j) { hi[j] = 0u; lo[j] = 0u; }
        }
        uint32_t off = (uint32_t)(r * 256 + ((kb ^ (r & 7)) * 16));
        *(uint4*)(smb + off)          = make_uint4(hi[0], hi[1], hi[2], hi[3]);
        *(uint4*)(smb + A_LO_B + off) = make_uint4(lo[0], lo[1], lo[2], lo[3]);
    }
    __syncthreads();

    const int q4 = lane >> 2;               // 0..7
    const int c2 = (lane & 3) * 2;

    // Hoisted A-fragment addressing
    const int m_  = lane >> 3, i2_ = lane & 7;
    const int kbh = m_ >> 1;
    const int rbase = (m_ & 1) * 8 + i2_;
    uint32_t arow[2], rx7[2];
#pragma unroll
    for (int mt = 0; mt < 2; ++mt) {
        int r = mt * 16 + rbase;
        arow[mt] = sb + (uint32_t)(r * 256);
        rx7[mt]  = (uint32_t)(r & 7);
    }

    // B fragments: head hh, wslots ch2*4 .. ch2*4+3
    const uint4* Bw = (const uint4*)Wt + (hh * 4096 + (ch2 * 4) * 256 + lane);

    // ---- GEMM: rows 0..31 x cols [ch2*64,+64) of head hh, all in one pass ----
    float acc[2][8][4];
#pragma unroll
    for (int mt = 0; mt < 2; ++mt)
#pragma unroll
        for (int n8 = 0; n8 < 8; ++n8)
#pragma unroll
            for (int j = 0; j < 4; ++j) acc[mt][n8][j] = 0.f;

#pragma unroll
    for (int kc = 0; kc < 8; ++kc) {
        const uint32_t kb = (uint32_t)(kc * 2 + kbh);
        uint32_t ahi[2][4], alo[2][4];
#pragma unroll
        for (int mt = 0; mt < 2; ++mt) {
            uint32_t addr = arow[mt] + ((kb ^ rx7[mt]) << 4);
            ldsm_x4(ahi[mt], addr);
            ldsm_x4(alo[mt], addr + A_LO_B);
        }
        uint4 b0 = Bw[kc * 32];
        uint4 b1 = Bw[kc * 32 + 256];
        uint4 b2 = Bw[kc * 32 + 512];
        uint4 b3 = Bw[kc * 32 + 768];
#pragma unroll
        for (int mt = 0; mt < 2; ++mt) {
            mma_bf16(acc[mt][0], ahi[mt], b0.x, b0.y);
            mma_bf16(acc[mt][1], ahi[mt], b0.z, b0.w);
            mma_bf16(acc[mt][2], ahi[mt], b1.x, b1.y);
            mma_bf16(acc[mt][3], ahi[mt], b1.z, b1.w);
            mma_bf16(acc[mt][4], ahi[mt], b2.x, b2.y);
            mma_bf16(acc[mt][5], ahi[mt], b2.z, b2.w);
            mma_bf16(acc[mt][6], ahi[mt], b3.x, b3.y);
            mma_bf16(acc[mt][7], ahi[mt], b3.z, b3.w);
            mma_bf16(acc[mt][0], alo[mt], b0.x, b0.y);
            mma_bf16(acc[mt][1], alo[mt], b0.z, b0.w);
            mma_bf16(acc[mt][2], alo[mt], b1.x, b1.y);
            mma_bf16(acc[mt][3], alo[mt], b1.z, b1.w);
            mma_bf16(acc[mt][4], alo[mt], b2.x, b2.y);
            mma_bf16(acc[mt][5], alo[mt], b2.z, b2.w);
            mma_bf16(acc[mt][6], alo[mt], b3.x, b3.y);
            mma_bf16(acc[mt][7], alo[mt], b3.z, b3.w);
        }
        uint4 l0 = Bw[kc * 32 + 2048];
        uint4 l1 = Bw[kc * 32 + 2304];
        uint4 l2 = Bw[kc * 32 + 2560];
        uint4 l3 = Bw[kc * 32 + 2816];
#pragma unroll
        for (int mt = 0; mt < 2; ++mt) {
            mma_bf16(acc[mt][0], ahi[mt], l0.x, l0.y);
            mma_bf16(acc[mt][1], ahi[mt], l0.z, l0.w);
            mma_bf16(acc[mt][2], ahi[mt], l1.x, l1.y);
            mma_bf16(acc[mt][3], ahi[mt], l1.z, l1.w);
            mma_bf16(acc[mt][4], ahi[mt], l2.x, l2.y);
            mma_bf16(acc[mt][5], ahi[mt], l2.z, l2.w);
            mma_bf16(acc[mt][6], ahi[mt], l3.x, l3.y);
            mma_bf16(acc[mt][7], ahi[mt], l3.z, l3.w);
        }
    }

    // ---- xp store (fp32, all heads) + logit partials from accumulators ----
    float pals[2][2], pald[2][2];
#pragma unroll
    for (int mt = 0; mt < 2; ++mt) { pals[mt][0]=pals[mt][1]=pald[mt][0]=pald[mt][1]=0.f; }
    float* xph = s_xp + hh * XP_HEAD;
#pragma unroll
    for (int mt = 0; mt < 2; ++mt) {
        int r0 = mt * 16 + q4;
#pragma unroll
        for (int n8 = 0; n8 < 8; ++n8) {
            int ch = ch2 * 64 + n8 * 8 + c2;          // col within head
            float a0 = s_att[hh * 128 + ch],       a1 = s_att[hh * 128 + ch + 1];
            float d0 = s_att[512 + hh * 128 + ch], d1 = s_att[512 + hh * 128 + ch + 1];
            pals[mt][0] = fmaf(acc[mt][n8][0], a0, fmaf(acc[mt][n8][1], a1, pals[mt][0]));
            pald[mt][0] = fmaf(acc[mt][n8][0], d0, fmaf(acc[mt][n8][1], d1, pald[mt][0]));
            pals[mt][1] = fmaf(acc[mt][n8][2], a0, fmaf(acc[mt][n8][3], a1, pals[mt][1]));
            pald[mt][1] = fmaf(acc[mt][n8][2], d0, fmaf(acc[mt][n8][3], d1, pald[mt][1]));
            *(float2*)(xph + r0 * XP_STRIDE + ch)       = make_float2(acc[mt][n8][0], acc[mt][n8][1]);
            *(float2*)(xph + (r0 + 8) * XP_STRIDE + ch) = make_float2(acc[mt][n8][2], acc[mt][n8][3]);
        }
    }
#pragma unroll
    for (int mt = 0; mt < 2; ++mt)
#pragma unroll
        for (int j = 0; j < 2; ++j) {
            pals[mt][j] += __shfl_xor_sync(0xffffffffu, pals[mt][j], 1);
            pals[mt][j] += __shfl_xor_sync(0xffffffffu, pals[mt][j], 2);
            pald[mt][j] += __shfl_xor_sync(0xffffffffu, pald[mt][j], 1);
            pald[mt][j] += __shfl_xor_sync(0xffffffffu, pald[mt][j], 2);
        }
    if ((lane & 3) == 0) {
#pragma unroll
        for (int mt = 0; mt < 2; ++mt) {
            int r0 = mt * 16 + q4;
            s_alsp[wid * 32 + r0]     = pals[mt][0];
            s_alsp[wid * 32 + r0 + 8] = pals[mt][1];
            s_aldp[wid * 32 + r0]     = pald[mt][0];
            s_aldp[wid * 32 + r0 + 8] = pald[mt][1];
        }
    }
    __syncthreads();

    // ---- segment softmax (120 workers: 4 heads x 3 inst x 10 dst) ----
    if (tid < 120) {
        int th = tid / 30, rem = tid - th * 30;
        int il = rem / 10, dst = rem - il * 10, rb = il * 10;
        const float* asl = s_alsp + th * 64;     // two 32-entry halves
        const float* adl = s_aldp + th * 64;
        int rd = rb + dst;
        float ald = adl[rd] + adl[32 + rd];
        int s0 = c_start[dst], s1 = c_start[dst + 1];
        float vb[5], m = -1e30f;
        for (int k = s0; k < s1; ++k) {
            int rs = rb + c_src[k];
            float als = asl[rs] + asl[32 + rs];
            float v = als + ald;
            v = v > 0.f ? v : 0.2f * v;
            vb[k - s0] = v;
            m = fmaxf(m, v);
        }
        float ssum = 0.f;
        for (int k = s0; k < s1; ++k) {
            float ex = __expf(vb[k - s0] - m);
            ssum += ex;
            s_alpha[(th * 3 + il) * NE + k] = ex;
        }
        float inv = 1.0f / ssum;
        for (int k = s0; k < s1; ++k) s_alpha[(th * 3 + il) * NE + k] *= inv;
    }
    __syncthreads();

    // ---- fused aggregation (all heads) + mean + bias + GELU + residual ----
#pragma unroll
    for (int it = 0; it < 4; ++it) {
        int q = tid + 256 * it;                 // 960 float4 tasks
        if (q < 960) {
            int il = q / 320, rem = q - il * 320, dst = rem >> 5, f = (rem & 31) * 4;
            long ig = blk * NI + il;
            if (ig < BT) {
                int rb = il * 10;
                int s0 = c_start[dst], s1 = c_start[dst + 1];
                float4 a4; a4.x = a4.y = a4.z = a4.w = 0.f;
#pragma unroll
                for (int th = 0; th < 4; ++th) {
                    const float* al = s_alpha + (th * 3 + il) * NE;
                    const float* xb = s_xp + th * XP_HEAD + f;
                    for (int k = s0; k < s1; ++k) {
                        int row = rb + c_src[k];
                        float a = al[k];
                        float4 xv = *(const float4*)(xb + row * XP_STRIDE);
                        a4.x = fmaf(a, xv.x, a4.x);
                        a4.y = fmaf(a, xv.y, a4.y);
                        a4.z = fmaf(a, xv.z, a4.z);
                        a4.w = fmaf(a, xv.w, a4.w);
                    }
                }
                float4 bgv = *(const float4*)(bg + f);
                float4 rs  = *(const float4*)(nf_in + ig * NODE_F + dst * HID + f);
                float4 w;
                w.x = gelu_exact(fmaf(0.25f, a4.x, bgv.x)) + rs.x;
                w.y = gelu_exact(fmaf(0.25f, a4.y, bgv.y)) + rs.y;
                w.z = gelu_exact(fmaf(0.25f, a4.z, bgv.z)) + rs.z;
                w.w = gelu_exact(fmaf(0.25f, a4.w, bgv.w)) + rs.w;
                *(float4*)(nf_out + ig * NODE_F + dst * HID + f) = w;
            }
        }
    }
}

// ---------------------------------------------------------------------------
extern "C" void kernel_launch(void* const* d_in, const int* in_sizes, int n_in,
                              void* d_out, int out_size)
{
    const float* x     = (const float*)d_in[0];
    const float* Wenc  = (const float*)d_in[1];
    const float* benc  = (const float*)d_in[2];
    const float* gamma = (const float*)d_in[3];
    const float* beta  = (const float*)d_in[4];
    const float* Wg    = (const float*)d_in[5];
    const float* asrc  = (const float*)d_in[6];
    const float* adst  = (const float*)d_in[7];
    const float* bg    = (const float*)d_in[8];

    float* out = (float*)d_out;
    float* region_out = (out_size >= 2 * NTOT) ? out + NTOT : nullptr;

    float* nf0;  cudaGetSymbolAddress((void**)&nf0, g_nf0);
    float* nf1;  cudaGetSymbolAddress((void**)&nf1, g_nf1);
    uint8_t* wt; cudaGetSymbolAddress((void**)&wt, g_Wt);

    cudaFuncSetAttribute(gat_mma_kernel, cudaFuncAttributeMaxDynamicSharedMemorySize, SM_DYNBYTES);

    wt_kernel<<<12, 256>>>(Wg);
    encoder_kernel<<<BT / 2, 256>>>(x, Wenc, benc, gamma, beta, nf0, region_out);

    gat_mma_kernel<<<GRID_GAT, 256, SM_DYNBYTES>>>(nf0, wt,               asrc,        adst,        bg,       nf1);
    gat_mma_kernel<<<GRID_GAT, 256, SM_DYNBYTES>>>(nf1, wt + 4 * 65536,   asrc + 512,  adst + 512,  bg + 128, nf0);
    gat_mma_kernel<<<GRID_GAT, 256, SM_DYNBYTES>>>(nf0, wt + 8 * 65536,   asrc + 1024, adst + 1024, bg + 256, out);
}

// round 12
// speedup vs baseline: 1.2530x; 1.1076x over previous
#include <cuda_runtime.h>
#include <cuda_bf16.h>
#include <cuda_fp16.h>
#include <math.h>
#include <stdint.h>

// Problem constants
#define R_NODES 10
#define HID 128
#define NE 36
#define BT 12800
#define NODE_F 1280
#define NTOT (BT * NODE_F)
#define LN_EPS 1e-5f
#define NI 3
#define VROWS 30
#define GRID_GAT ((BT + NI - 1) / NI)   // 4267

__device__ float g_nf0[NTOT];
__device__ float g_nf1[NTOT];
// W pre-arranged in mma.sync B-fragment layout:
// [layer][head]{ hi: [wslot(8)][kc(8)][lane(32)] 16B chunks = 32KB, lo: +32KB }
__device__ __align__(16) uint8_t g_Wt[3 * 4 * 65536];

__constant__ int c_start[R_NODES + 1] = {0, 5, 8, 12, 15, 17, 22, 27, 31, 33, 36};
__constant__ int c_src[NE] = {
    9, 5, 6, 1, 0,   0, 2, 1,   5, 1, 3, 2,   2, 4, 3,   3, 4,
    6, 2, 0, 7, 5,   5, 9, 0, 7, 6,   6, 5, 8, 7,   7, 8,   6, 0, 9
};

__device__ __forceinline__ float gelu_exact(float v) {
    return 0.5f * v * (1.0f + erff(v * 0.70710678118654752440f));
}
__device__ __forceinline__ uint32_t smem_u32(const void* p) {
    uint32_t a;
    asm("{ .reg .u64 t; cvta.to.shared.u64 t, %1; cvt.u32.u64 %0, t; }" : "=r"(a) : "l"(p));
    return a;
}
__device__ __forceinline__ void ldsm_x4(uint32_t* r, uint32_t addr) {
    asm volatile("ldmatrix.sync.aligned.m8n8.x4.shared.b16 {%0,%1,%2,%3}, [%4];"
                 : "=r"(r[0]), "=r"(r[1]), "=r"(r[2]), "=r"(r[3]) : "r"(addr));
}
__device__ __forceinline__ void mma_bf16(float* d, const uint32_t* a, uint32_t b0, uint32_t b1) {
    asm volatile("mma.sync.aligned.m16n8k16.row.col.f32.bf16.bf16.f32 "
                 "{%0,%1,%2,%3}, {%4,%5,%6,%7}, {%8,%9}, {%0,%1,%2,%3};"
                 : "+f"(d[0]), "+f"(d[1]), "+f"(d[2]), "+f"(d[3])
                 : "r"(a[0]), "r"(a[1]), "r"(a[2]), "r"(a[3]), "r"(b0), "r"(b1));
}
__device__ __forceinline__ void split_bf16x2(float v0, float v1, uint32_t& hi, uint32_t& lo) {
    __nv_bfloat16 h0 = __float2bfloat16(v0);
    __nv_bfloat16 h1 = __float2bfloat16(v1);
    __nv_bfloat16 l0 = __float2bfloat16(v0 - __bfloat162float(h0));
    __nv_bfloat16 l1 = __float2bfloat16(v1 - __bfloat162float(h1));
    hi = (uint32_t)__bfloat16_as_ushort(h0) | ((uint32_t)__bfloat16_as_ushort(h1) << 16);
    lo = (uint32_t)__bfloat16_as_ushort(l0) | ((uint32_t)__bfloat16_as_ushort(l1) << 16);
}

// ---------------------------------------------------------------------------
// W prep (unchanged)
// ---------------------------------------------------------------------------
__global__ void wt_kernel(const float* __restrict__ Wg) {
    int l = blockIdx.x >> 2, h = blockIdx.x & 3;
    uint8_t* base = g_Wt + (size_t)(l * 4 + h) * 65536;
    const float* W = Wg + l * 65536 + h * 128;   // W[k*512 + n]
    for (int c = threadIdx.x; c < 2048; c += 256) {
        int ws = c >> 8, kc = (c >> 5) & 7, lane = c & 31;
        int n0 = ws * 16 + (lane >> 2);
        int k0 = kc * 16 + 2 * (lane & 3);
        uint32_t hi[4], lo[4];
#pragma unroll
        for (int j = 0; j < 4; ++j) {
            int n = n0 + (j >> 1) * 8;
            int k = k0 + (j & 1) * 8;
            float w0 = W[k * 512 + n];
            float w1 = W[(k + 1) * 512 + n];
            split_bf16x2(w0, w1, hi[j], lo[j]);
        }
        *(uint4*)(base + c * 16)         = make_uint4(hi[0], hi[1], hi[2], hi[3]);
        *(uint4*)(base + 32768 + c * 16) = make_uint4(lo[0], lo[1], lo[2], lo[3]);
    }
}

// ---------------------------------------------------------------------------
// Encoder (unchanged)
// ---------------------------------------------------------------------------
__global__ void __launch_bounds__(256) encoder_kernel(
    const float* __restrict__ x, const float* __restrict__ Wenc,
    const float* __restrict__ benc, const float* __restrict__ gamma,
    const float* __restrict__ beta, float* __restrict__ nf_out,
    float* __restrict__ region_out)
{
    const int tid = threadIdx.x;
    const int lane = tid & 31;
    const int w4 = (tid >> 5) & 3;
    const int inst = tid >> 7;
    const long bt = (long)blockIdx.x * 2 + inst;
    const float* xr = x + bt * (R_NODES * 6);
    float* outp = nf_out + bt * NODE_F;
    float* regp = region_out ? region_out + bt * NODE_F : nullptr;

    for (int r = w4; r < R_NODES; r += 4) {
        float xv[6];
#pragma unroll
        for (int c = 0; c < 6; ++c) xv[c] = xr[r * 6 + c];
        float h[4];
#pragma unroll
        for (int j = 0; j < 4; ++j) {
            int k = lane + 32 * j;
            float a = benc[r * HID + k];
#pragma unroll
            for (int c = 0; c < 6; ++c) a = fmaf(xv[c], Wenc[(r * 6 + c) * HID + k], a);
            h[j] = a;
        }
        float s = h[0] + h[1] + h[2] + h[3];
        float sq = h[0]*h[0] + h[1]*h[1] + h[2]*h[2] + h[3]*h[3];
#pragma unroll
        for (int o = 16; o > 0; o >>= 1) {
            s  += __shfl_xor_sync(0xffffffffu, s, o);
            sq += __shfl_xor_sync(0xffffffffu, sq, o);
        }
        float mean = s * (1.0f / 128.0f);
        float var = sq * (1.0f / 128.0f) - mean * mean;
        float rstd = rsqrtf(var + LN_EPS);
#pragma unroll
        for (int j = 0; j < 4; ++j) {
            int k = lane + 32 * j;
            float v = (h[j] - mean) * rstd * gamma[r * HID + k] + beta[r * HID + k];
            float g = gelu_exact(v);
            outp[r * HID + k] = g;
            if (regp) regp[r * HID + k] = g;
        }
    }
}

// ---------------------------------------------------------------------------
// GAT layer: single-pass all-4-heads GEMM, two register-local col sub-passes
// per warp (32 cols each), xp stored as half2. 3 instances/CTA, 3 CTAs/SM.
// Phases: A-fill -> sync -> GEMM+xp+partials -> sync -> softmax -> sync ->
//         fused agg+mean+bias+GELU+residual -> gmem.
// smem byte map (58048):
//   0      A_hi (8192)      8192   A_lo (8192)
//   16384  xp half2 [4][32][66 u32] = 33792
//   50176  att (4096)
//   54272  alsp (1024)      55296  aldp (1024)
//   56320  alpha (1728)
// ---------------------------------------------------------------------------
#define A_LO_B   8192
#define XP_B     16384
#define XPS_U32  66
#define XPH_U32  (32 * XPS_U32)
#define ATT_B    50176
#define ALSP_B   54272
#define ALDP_B   55296
#define ALPHA_B  56320
#define SM_DYNBYTES 58048

__global__ void __launch_bounds__(256, 3) gat_mma_kernel(
    const float* __restrict__ nf_in, const uint8_t* __restrict__ Wt,
    const float* __restrict__ asrc, const float* __restrict__ adst,
    const float* __restrict__ bg, float* __restrict__ nf_out)
{
    extern __shared__ uint8_t smb[];
    const uint32_t sb = smem_u32(smb);
    __half2* s_xph = (__half2*)(smb + XP_B);
    float* s_att   = (float*)(smb + ATT_B);
    float* s_alsp  = (float*)(smb + ALSP_B);
    float* s_aldp  = (float*)(smb + ALDP_B);
    float* s_alpha = (float*)(smb + ALPHA_B);

    const int tid  = threadIdx.x;
    const int wid  = tid >> 5;
    const int lane = tid & 31;
    const int hh   = wid >> 1;          // head 0..3
    const int ch2  = wid & 1;           // col half: cols ch2*64..+64 within head
    const long blk = blockIdx.x;

    for (int i = tid; i < 512; i += 256) {
        s_att[i]       = asrc[i];
        s_att[512 + i] = adst[i];
    }

    // A fill: 32 rows x 16 k-chunks = 512 tasks -> bf16 hi/lo swizzled
#pragma unroll
    for (int it = 0; it < 2; ++it) {
        int t = tid + 256 * it;
        int r = t >> 4, kb = t & 15;
        int il = r / 10, node = r - il * 10;
        long ig = blk * NI + il;
        uint32_t hi[4], lo[4];
        if (r < VROWS && ig < BT) {
            const float* src = nf_in + ig * NODE_F + node * HID + kb * 8;
            float4 a = *(const float4*)(src);
            float4 b = *(const float4*)(src + 4);
            split_bf16x2(a.x, a.y, hi[0], lo[0]);
            split_bf16x2(a.z, a.w, hi[1], lo[1]);
            split_bf16x2(b.x, b.y, hi[2], lo[2]);
            split_bf16x2(b.z, b.w, hi[3], lo[3]);
        } else {
#pragma unroll
            for (int j = 0; j < 4; ++j) { hi[j] = 0u; lo[j] = 0u; }
        }
        uint32_t off = (uint32_t)(r * 256 + ((kb ^ (r & 7)) * 16));
        *(uint4*)(smb + off)          = make_uint4(hi[0], hi[1], hi[2], hi[3]);
        *(uint4*)(smb + A_LO_B + off) = make_uint4(lo[0], lo[1], lo[2], lo[3]);
    }
    __syncthreads();

    const int q4 = lane >> 2;
    const int c2 = (lane & 3) * 2;

    // Hoisted A-fragment addressing
    const int m_  = lane >> 3, i2_ = lane & 7;
    const int kbh = m_ >> 1;
    const int rbase = (m_ & 1) * 8 + i2_;
    uint32_t arow[2], rx7[2];
#pragma unroll
    for (int mt = 0; mt < 2; ++mt) {
        int r = mt * 16 + rbase;
        arow[mt] = sb + (uint32_t)(r * 256);
        rx7[mt]  = (uint32_t)(r & 7);
    }

    // ---- GEMM: two 32-col sub-passes, acc register-local per pass ----
    float pals[2][2], pald[2][2];
    pals[0][0]=pals[0][1]=pals[1][0]=pals[1][1]=0.f;
    pald[0][0]=pald[0][1]=pald[1][0]=pald[1][1]=0.f;
    __half2* xph = s_xph + hh * XPH_U32;

#pragma unroll
    for (int s = 0; s < 2; ++s) {
        const uint4* Bw = (const uint4*)Wt + (hh * 4096 + (ch2 * 4 + s * 2) * 256 + lane);
        float acc[2][4][4];
#pragma unroll
        for (int mt = 0; mt < 2; ++mt)
#pragma unroll
            for (int n8 = 0; n8 < 4; ++n8)
#pragma unroll
                for (int j = 0; j < 4; ++j) acc[mt][n8][j] = 0.f;

#pragma unroll
        for (int kc = 0; kc < 8; ++kc) {
            const uint32_t kb = (uint32_t)(kc * 2 + kbh);
            uint32_t ahi[2][4], alo[2][4];
#pragma unroll
            for (int mt = 0; mt < 2; ++mt) {
                uint32_t addr = arow[mt] + ((kb ^ rx7[mt]) << 4);
                ldsm_x4(ahi[mt], addr);
                ldsm_x4(alo[mt], addr + A_LO_B);
            }
            uint4 b0 = Bw[kc * 32];
            uint4 b1 = Bw[kc * 32 + 256];
            uint4 l0 = Bw[kc * 32 + 2048];
            uint4 l1 = Bw[kc * 32 + 2304];
#pragma unroll
            for (int mt = 0; mt < 2; ++mt) {
                mma_bf16(acc[mt][0], ahi[mt], b0.x, b0.y);
                mma_bf16(acc[mt][1], ahi[mt], b0.z, b0.w);
                mma_bf16(acc[mt][2], ahi[mt], b1.x, b1.y);
                mma_bf16(acc[mt][3], ahi[mt], b1.z, b1.w);
                mma_bf16(acc[mt][0], alo[mt], b0.x, b0.y);
                mma_bf16(acc[mt][1], alo[mt], b0.z, b0.w);
                mma_bf16(acc[mt][2], alo[mt], b1.x, b1.y);
                mma_bf16(acc[mt][3], alo[mt], b1.z, b1.w);
                mma_bf16(acc[mt][0], ahi[mt], l0.x, l0.y);
                mma_bf16(acc[mt][1], ahi[mt], l0.z, l0.w);
                mma_bf16(acc[mt][2], ahi[mt], l1.x, l1.y);
                mma_bf16(acc[mt][3], ahi[mt], l1.z, l1.w);
            }
        }

        // xp store (half2) + logit partials from accumulators
#pragma unroll
        for (int mt = 0; mt < 2; ++mt) {
            int r0 = mt * 16 + q4;
#pragma unroll
            for (int n8 = 0; n8 < 4; ++n8) {
                int ch = ch2 * 64 + s * 32 + n8 * 8 + c2;
                float a0 = s_att[hh * 128 + ch],       a1 = s_att[hh * 128 + ch + 1];
                float d0 = s_att[512 + hh * 128 + ch], d1 = s_att[512 + hh * 128 + ch + 1];
                pals[mt][0] = fmaf(acc[mt][n8][0], a0, fmaf(acc[mt][n8][1], a1, pals[mt][0]));
                pald[mt][0] = fmaf(acc[mt][n8][0], d0, fmaf(acc[mt][n8][1], d1, pald[mt][0]));
                pals[mt][1] = fmaf(acc[mt][n8][2], a0, fmaf(acc[mt][n8][3], a1, pals[mt][1]));
                pald[mt][1] = fmaf(acc[mt][n8][2], d0, fmaf(acc[mt][n8][3], d1, pald[mt][1]));
                xph[r0 * XPS_U32 + (ch >> 1)]       = __floats2half2_rn(acc[mt][n8][0], acc[mt][n8][1]);
                xph[(r0 + 8) * XPS_U32 + (ch >> 1)] = __floats2half2_rn(acc[mt][n8][2], acc[mt][n8][3]);
            }
        }
    }

#pragma unroll
    for (int mt = 0; mt < 2; ++mt)
#pragma unroll
        for (int j = 0; j < 2; ++j) {
            pals[mt][j] += __shfl_xor_sync(0xffffffffu, pals[mt][j], 1);
            pals[mt][j] += __shfl_xor_sync(0xffffffffu, pals[mt][j], 2);
            pald[mt][j] += __shfl_xor_sync(0xffffffffu, pald[mt][j], 1);
            pald[mt][j] += __shfl_xor_sync(0xffffffffu, pald[mt][j], 2);
        }
    if ((lane & 3) == 0) {
#pragma unroll
        for (int mt = 0; mt < 2; ++mt) {
            int r0 = mt * 16 + q4;
            s_alsp[wid * 32 + r0]     = pals[mt][0];
            s_alsp[wid * 32 + r0 + 8] = pals[mt][1];
            s_aldp[wid * 32 + r0]     = pald[mt][0];
            s_aldp[wid * 32 + r0 + 8] = pald[mt][1];
        }
    }
    __syncthreads();

    // ---- segment softmax (120 workers: 4 heads x 3 inst x 10 dst) ----
    if (tid < 120) {
        int th = tid / 30, rem = tid - th * 30;
        int il = rem / 10, dst = rem - il * 10, rb = il * 10;
        const float* asl = s_alsp + th * 64;
        const float* adl = s_aldp + th * 64;
        int rd = rb + dst;
        float ald = adl[rd] + adl[32 + rd];
        int s0 = c_start[dst], s1 = c_start[dst + 1];
        float vb[5], m = -1e30f;
        for (int k = s0; k < s1; ++k) {
            int rs = rb + c_src[k];
            float als = asl[rs] + asl[32 + rs];
            float v = als + ald;
            v = v > 0.f ? v : 0.2f * v;
            vb[k - s0] = v;
            m = fmaxf(m, v);
        }
        float ssum = 0.f;
        for (int k = s0; k < s1; ++k) {
            float ex = __expf(vb[k - s0] - m);
            ssum += ex;
            s_alpha[(th * 3 + il) * NE + k] = ex;
        }
        float inv = 1.0f / ssum;
        for (int k = s0; k < s1; ++k) s_alpha[(th * 3 + il) * NE + k] *= inv;
    }
    __syncthreads();

    // ---- fused aggregation (all heads) + mean + bias + GELU + residual ----
#pragma unroll
    for (int it = 0; it < 4; ++it) {
        int q = tid + 256 * it;                 // 960 float4 tasks
        if (q < 960) {
            int il = q / 320, rem = q - il * 320, dst = rem >> 5, f = (rem & 31) * 4;
            long ig = blk * NI + il;
            if (ig < BT) {
                int rb = il * 10;
                int s0 = c_start[dst], s1 = c_start[dst + 1];
                float4 a4; a4.x = a4.y = a4.z = a4.w = 0.f;
#pragma unroll
                for (int th = 0; th < 4; ++th) {
                    const float* al = s_alpha + (th * 3 + il) * NE;
                    const __half2* xb = s_xph + th * XPH_U32 + (f >> 1);
                    for (int k = s0; k < s1; ++k) {
                        int row = rb + c_src[k];
                        float a = al[k];
                        __half2 p0 = xb[row * XPS_U32];
                        __half2 p1 = xb[row * XPS_U32 + 1];
                        float2 f0 = __half22float2(p0);
                        float2 f1 = __half22float2(p1);
                        a4.x = fmaf(a, f0.x, a4.x);
                        a4.y = fmaf(a, f0.y, a4.y);
                        a4.z = fmaf(a, f1.x, a4.z);
                        a4.w = fmaf(a, f1.y, a4.w);
                    }
                }
                float4 bgv = *(const float4*)(bg + f);
                float4 rs  = *(const float4*)(nf_in + ig * NODE_F + dst * HID + f);
                float4 w;
                w.x = gelu_exact(fmaf(0.25f, a4.x, bgv.x)) + rs.x;
                w.y = gelu_exact(fmaf(0.25f, a4.y, bgv.y)) + rs.y;
                w.z = gelu_exact(fmaf(0.25f, a4.z, bgv.z)) + rs.z;
                w.w = gelu_exact(fmaf(0.25f, a4.w, bgv.w)) + rs.w;
                *(float4*)(nf_out + ig * NODE_F + dst * HID + f) = w;
            }
        }
    }
}

// ---------------------------------------------------------------------------
extern "C" void kernel_launch(void* const* d_in, const int* in_sizes, int n_in,
                              void* d_out, int out_size)
{
    const float* x     = (const float*)d_in[0];
    const float* Wenc  = (const float*)d_in[1];
    const float* benc  = (const float*)d_in[2];
    const float* gamma = (const float*)d_in[3];
    const float* beta  = (const float*)d_in[4];
    const float* Wg    = (const float*)d_in[5];
    const float* asrc  = (const float*)d_in[6];
    const float* adst  = (const float*)d_in[7];
    const float* bg    = (const float*)d_in[8];

    float* out = (float*)d_out;
    float* region_out = (out_size >= 2 * NTOT) ? out + NTOT : nullptr;

    float* nf0;  cudaGetSymbolAddress((void**)&nf0, g_nf0);
    float* nf1;  cudaGetSymbolAddress((void**)&nf1, g_nf1);
    uint8_t* wt; cudaGetSymbolAddress((void**)&wt, g_Wt);

    cudaFuncSetAttribute(gat_mma_kernel, cudaFuncAttributeMaxDynamicSharedMemorySize, SM_DYNBYTES);

    wt_kernel<<<12, 256>>>(Wg);
    encoder_kernel<<<BT / 2, 256>>>(x, Wenc, benc, gamma, beta, nf0, region_out);

    gat_mma_kernel<<<GRID_GAT, 256, SM_DYNBYTES>>>(nf0, wt,               asrc,        adst,        bg,       nf1);
    gat_mma_kernel<<<GRID_GAT, 256, SM_DYNBYTES>>>(nf1, wt + 4 * 65536,   asrc + 512,  adst + 512,  bg + 128, nf0);
    gat_mma_kernel<<<GRID_GAT, 256, SM_DYNBYTES>>>(nf0, wt + 8 * 65536,   asrc + 1024, adst + 1024, bg + 256, out);
}